// round 1
// baseline (speedup 1.0000x reference)
#include <cuda_runtime.h>

#define NN 2048
#define AG 5
#define ST 128
#define CO 64
#define UN 32
#define LOG2F_ 0.69314718055994530942f

// Scratch (no cudaMalloc allowed): averaged post-activation embeddings.
// g_M1T is stored transposed [u][n] so the JSD kernel can do float4 loads
// along the n (j) dimension. g_M2 stays row-major [n][u].
__device__ float g_M1T[UN * NN];
__device__ float g_M2[NN * UN];

// ---------------------------------------------------------------------------
// Kernel 1: dual embeddings + leaky_relu + agent-mean.
// M1[n] = (1/5) sum_a leaky_relu(state[n,a,:] @ W1 + b1)
// M2[n] = (1/5) sum_a leaky_relu(action[n,a,:] @ W2 + b2)
// Block = 128 threads (4 warps), each warp handles one sample n (lane = unit).
// ---------------------------------------------------------------------------
__global__ void embed_kernel(const float* __restrict__ state,
                             const float* __restrict__ action,
                             const float* __restrict__ W1,
                             const float* __restrict__ b1,
                             const float* __restrict__ W2,
                             const float* __restrict__ b2) {
    __shared__ float sW1[ST * UN];          // 16 KB
    __shared__ float sW2[CO * UN];          // 8 KB
    __shared__ float sb1[UN], sb2[UN];
    __shared__ float sstate[4 * AG * ST];   // 10 KB
    __shared__ float sact[4 * AG * CO];     // 5 KB

    const int tid = threadIdx.x;
    for (int i = tid; i < ST * UN; i += 128) sW1[i] = W1[i];
    for (int i = tid; i < CO * UN; i += 128) sW2[i] = W2[i];
    if (tid < UN) { sb1[tid] = b1[tid]; sb2[tid] = b2[tid]; }

    const int nb = blockIdx.x * 4;
    const float* sbase = state + (size_t)nb * AG * ST;
    const float* abase = action + (size_t)nb * AG * CO;
    for (int i = tid; i < 4 * AG * ST; i += 128) sstate[i] = sbase[i];
    for (int i = tid; i < 4 * AG * CO; i += 128) sact[i] = abase[i];
    __syncthreads();

    const int w = tid >> 5;     // local sample 0..3
    const int u = tid & 31;     // unit
    const int n = nb + w;

    float sum1 = 0.f;
    #pragma unroll
    for (int a = 0; a < AG; a++) {
        float acc = sb1[u];
        const float* srow = &sstate[w * AG * ST + a * ST];
        #pragma unroll 16
        for (int s = 0; s < ST; s++)
            acc = fmaf(srow[s], sW1[s * UN + u], acc);
        sum1 += (acc > 0.f) ? acc : 0.01f * acc;   // leaky_relu(0.01)
    }
    g_M1T[u * NN + n] = 0.2f * sum1;

    float sum2 = 0.f;
    #pragma unroll
    for (int a = 0; a < AG; a++) {
        float acc = sb2[u];
        const float* arow = &sact[w * AG * CO + a * CO];
        #pragma unroll 16
        for (int c = 0; c < CO; c++)
            acc = fmaf(arow[c], sW2[c * UN + u], acc);
        sum2 += (acc > 0.f) ? acc : 0.01f * acc;
    }
    g_M2[n * UN + u] = 0.2f * sum2;
}

// Numerically stable softplus(x) = max(x,0) + log(1 + exp(-|x|))
__device__ __forceinline__ float softplus_f(float x) {
    float a = fabsf(x);
    float e = __expf(-a);
    float l = __logf(1.f + e);
    return fmaxf(x, 0.f) + l;
}

// ---------------------------------------------------------------------------
// Kernel 2: fused tiny-K GEMM (u_pool[i,j] = M2[i] . M1[j]) + JSD reductions.
// Never materializes the 2048x2048 matrix.
// Block = 256 threads. i-tile of 8 rows per block; each thread owns 8
// consecutive j columns -> 8x8 register accumulator tile.
// E_neg[i,j] = softplus(u) - log2;  E_pos[i,i] = log2 - softplus(u_ii) + u_ii
// loss[i] = (sum_{j!=i} softplus(u_ij) - 2047*log2)/2047 - E_pos[i]
// ---------------------------------------------------------------------------
__global__ void jsd_kernel(float* __restrict__ out) {
    __shared__ __align__(16) float sm2T[UN * 8];  // M2 tile, transposed [u][ii]
    __shared__ float sdiag[8];                     // raw u_ii per tile row
    __shared__ float swsum[8][8];                  // [warp][ii] partial sums

    const int tid = threadIdx.x;
    const int i0 = blockIdx.x * 8;

    // Stage transposed M2 tile: sm2T[u*8 + ii] = M2[i0+ii][u]
    {
        int u = tid >> 3, ii = tid & 7;
        sm2T[tid] = g_M2[(i0 + ii) * UN + u];
    }
    __syncthreads();

    float acc[8][8];
    #pragma unroll
    for (int a = 0; a < 8; a++)
        #pragma unroll
        for (int b = 0; b < 8; b++) acc[a][b] = 0.f;

    const int j0 = tid * 8;
    const float* bbase = g_M1T + j0;

    #pragma unroll 8
    for (int u = 0; u < UN; u++) {
        const float4* ap = (const float4*)&sm2T[u * 8];
        float4 a0 = ap[0];
        float4 a1 = ap[1];
        const float4* bp = (const float4*)(bbase + u * NN);
        float4 b0 = bp[0];
        float4 b1 = bp[1];
        float av[8] = {a0.x, a0.y, a0.z, a0.w, a1.x, a1.y, a1.z, a1.w};
        float bv[8] = {b0.x, b0.y, b0.z, b0.w, b1.x, b1.y, b1.z, b1.w};
        #pragma unroll
        for (int ii = 0; ii < 8; ii++)
            #pragma unroll
            for (int jj = 0; jj < 8; jj++)
                acc[ii][jj] = fmaf(av[ii], bv[jj], acc[ii][jj]);
    }

    // Per-thread softplus + row partial sums (diag included, subtracted later)
    float negsum[8];
    #pragma unroll
    for (int ii = 0; ii < 8; ii++) {
        float s = 0.f;
        #pragma unroll
        for (int jj = 0; jj < 8; jj++) {
            float x = acc[ii][jj];
            s += softplus_f(x);
            if (j0 + jj == i0 + ii) sdiag[ii] = x;   // exactly one writer
        }
        negsum[ii] = s;
    }

    // Reduce 256 threads -> 1 per tile row
    const int lane = tid & 31, wid = tid >> 5;
    #pragma unroll
    for (int ii = 0; ii < 8; ii++) {
        float v = negsum[ii];
        v += __shfl_down_sync(0xffffffffu, v, 16);
        v += __shfl_down_sync(0xffffffffu, v, 8);
        v += __shfl_down_sync(0xffffffffu, v, 4);
        v += __shfl_down_sync(0xffffffffu, v, 2);
        v += __shfl_down_sync(0xffffffffu, v, 1);
        if (lane == 0) swsum[wid][ii] = v;
    }
    __syncthreads();

    if (tid < 8) {
        float tot = 0.f;
        #pragma unroll
        for (int w = 0; w < 8; w++) tot += swsum[w][tid];
        float ud  = sdiag[tid];
        float spd = softplus_f(ud);
        float sum_off = tot - spd;                              // sum_{j!=i} softplus(u_ij)
        float Eneg = (sum_off - 2047.f * LOG2F_) * (1.f / 2047.f);
        float Epos = LOG2F_ - spd + ud;
        int i = i0 + tid;
        out[i]      = Eneg - Epos;   // loss
        out[NN + i] = Epos;          // MI
    }
}

extern "C" void kernel_launch(void* const* d_in, const int* in_sizes, int n_in,
                              void* d_out, int out_size) {
    const float* state  = (const float*)d_in[0];
    const float* action = (const float*)d_in[1];
    const float* W1     = (const float*)d_in[2];
    const float* b1     = (const float*)d_in[3];
    const float* W2     = (const float*)d_in[4];
    const float* b2     = (const float*)d_in[5];
    float* out = (float*)d_out;

    embed_kernel<<<NN / 4, 128>>>(state, action, W1, b1, W2, b2);
    jsd_kernel<<<NN / 8, 256>>>(out);
}

// round 2
// speedup vs baseline: 1.2480x; 1.2480x over previous
#include <cuda_runtime.h>

#define NN 2048
#define LOG2F_ 0.69314718055994530942f

typedef unsigned long long ull;

// Scratch (__device__ globals; no cudaMalloc allowed)
__device__ __align__(16) float g_M1T[32 * NN];   // [u][n] averaged em1, transposed
__device__ __align__(16) float g_M2[NN * 32];    // [n][u] averaged em2
__device__ float g_partial[2 * NN];              // softplus row-sums per j-half
__device__ float g_diag[NN];                     // raw u_ii

// ---- packed f32x2 helpers (FFMA2 path; see SASS_QUICKREF: only via PTX) ----
__device__ __forceinline__ ull pack2(float x, float y) {
    ull r;
    asm("mov.b64 %0, {%1, %2};" : "=l"(r) : "r"(__float_as_uint(x)), "r"(__float_as_uint(y)));
    return r;
}
__device__ __forceinline__ void unpack2(ull v, float& x, float& y) {
    unsigned lo, hi;
    asm("mov.b64 {%0, %1}, %2;" : "=r"(lo), "=r"(hi) : "l"(v));
    x = __uint_as_float(lo); y = __uint_as_float(hi);
}
__device__ __forceinline__ ull ffma2(ull a, ull b, ull c) {
    ull d;
    asm("fma.rn.f32x2 %0, %1, %2, %3;" : "=l"(d) : "l"(a), "l"(b), "l"(c));
    return d;
}

// stable softplus(x) = max(x,0) + log(1 + exp(-|x|))
__device__ __forceinline__ float softplus_f(float x) {
    float a = fabsf(x);
    float l = __logf(1.f + __expf(-a));
    return fmaxf(x, 0.f) + l;
}

// ---------------------------------------------------------------------------
// Kernel 1: embeddings + leaky_relu + agent-mean. Agent-fused inner loop:
// one weight LDS.64 feeds 5 agents x 2 units via FFMA2 (5 independent chains).
// grid 128 x 256 thr; thread = (n_local 0..15, uh 0..15 -> units u0,u0+1).
// ---------------------------------------------------------------------------
__global__ void __launch_bounds__(256) embed_kernel(
    const float* __restrict__ state, const float* __restrict__ action,
    const float* __restrict__ W1, const float* __restrict__ b1,
    const float* __restrict__ W2, const float* __restrict__ b2) {
    __shared__ __align__(16) float sW1[128 * 32];   // 16 KB
    __shared__ __align__(16) float sW2[64 * 32];    //  8 KB
    __shared__ __align__(8)  float sb1[32], sb2[32];

    const int tid = threadIdx.x;
    for (int i = tid; i < 128 * 32; i += 256) sW1[i] = W1[i];
    for (int i = tid; i < 64 * 32; i += 256)  sW2[i] = W2[i];
    if (tid < 32) { sb1[tid] = b1[tid]; sb2[tid] = b2[tid]; }
    __syncthreads();

    const int nl = tid >> 4, uh = tid & 15, u0 = uh * 2;
    const int n = blockIdx.x * 16 + nl;

    // ---------------- GEMM1: state [n,5,128] @ W1 [128,32] ----------------
    {
        const float* base = state + (size_t)n * 5 * 128;
        ull bias = *(const ull*)&sb1[u0];
        ull acc[5];
        #pragma unroll
        for (int a = 0; a < 5; a++) acc[a] = bias;

        #pragma unroll 4
        for (int k4 = 0; k4 < 32; k4++) {
            float4 x[5];
            #pragma unroll
            for (int a = 0; a < 5; a++)
                x[a] = *(const float4*)(base + a * 128 + k4 * 4);
            float xs[5][4];
            #pragma unroll
            for (int a = 0; a < 5; a++) {
                xs[a][0] = x[a].x; xs[a][1] = x[a].y;
                xs[a][2] = x[a].z; xs[a][3] = x[a].w;
            }
            #pragma unroll
            for (int kk = 0; kk < 4; kk++) {
                ull w = *(const ull*)&sW1[(k4 * 4 + kk) * 32 + u0];
                #pragma unroll
                for (int a = 0; a < 5; a++)
                    acc[a] = ffma2(pack2(xs[a][kk], xs[a][kk]), w, acc[a]);
            }
        }
        float mx = 0.f, my = 0.f;
        #pragma unroll
        for (int a = 0; a < 5; a++) {
            float vx, vy; unpack2(acc[a], vx, vy);
            mx += (vx > 0.f) ? vx : 0.01f * vx;     // leaky_relu(0.01)
            my += (vy > 0.f) ? vy : 0.01f * vy;
        }
        g_M1T[u0 * NN + n]       = 0.2f * mx;
        g_M1T[(u0 + 1) * NN + n] = 0.2f * my;
    }

    // ---------------- GEMM2: action [n,5,64] @ W2 [64,32] ----------------
    {
        const float* base = action + (size_t)n * 5 * 64;
        ull bias = *(const ull*)&sb2[u0];
        ull acc[5];
        #pragma unroll
        for (int a = 0; a < 5; a++) acc[a] = bias;

        #pragma unroll 4
        for (int k4 = 0; k4 < 16; k4++) {
            float4 x[5];
            #pragma unroll
            for (int a = 0; a < 5; a++)
                x[a] = *(const float4*)(base + a * 64 + k4 * 4);
            float xs[5][4];
            #pragma unroll
            for (int a = 0; a < 5; a++) {
                xs[a][0] = x[a].x; xs[a][1] = x[a].y;
                xs[a][2] = x[a].z; xs[a][3] = x[a].w;
            }
            #pragma unroll
            for (int kk = 0; kk < 4; kk++) {
                ull w = *(const ull*)&sW2[(k4 * 4 + kk) * 32 + u0];
                #pragma unroll
                for (int a = 0; a < 5; a++)
                    acc[a] = ffma2(pack2(xs[a][kk], xs[a][kk]), w, acc[a]);
            }
        }
        float mx = 0.f, my = 0.f;
        #pragma unroll
        for (int a = 0; a < 5; a++) {
            float vx, vy; unpack2(acc[a], vx, vy);
            mx += (vx > 0.f) ? vx : 0.01f * vx;
            my += (vy > 0.f) ? vy : 0.01f * vy;
        }
        *(float2*)&g_M2[n * 32 + u0] = make_float2(0.2f * mx, 0.2f * my);
    }
}

// ---------------------------------------------------------------------------
// Kernel 2: fused GEMM (u[i,j] = M2[i].M1[j], K=32) + softplus row-sums.
// grid 256: block = (i-tile ib of 16 rows) x (j-half h of 1024 cols).
// j processed in 4 chunks of 256 staged in smem. Thread = (ti 0..3, tj 0..63)
// owns 4i x 4j accumulated as 8 f32x2 (pairs along i). Row-sums reduced
// across threads and written to g_partial; raw diagonal to g_diag.
// ---------------------------------------------------------------------------
__global__ void __launch_bounds__(256) jsd_kernel() {
    __shared__ __align__(16) float sA[32 * 16];    // [u][ii]  2 KB
    __shared__ __align__(16) float sB[32 * 256];   // [u][jj] 32 KB
    __shared__ float swsum[8][4];

    const int tid = threadIdx.x;
    const int ib = blockIdx.x >> 1, h = blockIdx.x & 1;
    const int i0 = ib * 16, jb = h * 1024;
    const int ti = tid >> 6, tj = tid & 63;

    // stage transposed A tile: sA[u*16+ii] = M2[i0+ii][u]
    for (int t = tid; t < 512; t += 256) {
        int u = t >> 4, ii = t & 15;
        sA[u * 16 + ii] = g_M2[(i0 + ii) * 32 + u];
    }

    float rowsum[4] = {0.f, 0.f, 0.f, 0.f};

    for (int c = 0; c < 4; c++) {
        __syncthreads();
        const int j0c = jb + c * 256;
        // stage B chunk: 32 u-rows x 256 j, coalesced float4
        #pragma unroll
        for (int t = 0; t < 8; t++) {
            int idx = tid + t * 256;                 // 0..2047
            int u = idx >> 6, f = (idx & 63) * 4;
            *(float4*)&sB[u * 256 + f] = *(const float4*)&g_M1T[u * NN + j0c + f];
        }
        __syncthreads();

        ull acc[8];
        #pragma unroll
        for (int q = 0; q < 8; q++) acc[q] = 0ull;

        #pragma unroll 8
        for (int u = 0; u < 32; u++) {
            ull a01 = *(const ull*)&sA[u * 16 + ti * 4];
            ull a23 = *(const ull*)&sA[u * 16 + ti * 4 + 2];
            float4 b = *(const float4*)&sB[u * 256 + tj * 4];
            ull b0 = pack2(b.x, b.x), b1v = pack2(b.y, b.y);
            ull b2 = pack2(b.z, b.z), b3v = pack2(b.w, b.w);
            acc[0] = ffma2(a01, b0,  acc[0]);
            acc[1] = ffma2(a01, b1v, acc[1]);
            acc[2] = ffma2(a01, b2,  acc[2]);
            acc[3] = ffma2(a01, b3v, acc[3]);
            acc[4] = ffma2(a23, b0,  acc[4]);
            acc[5] = ffma2(a23, b1v, acc[5]);
            acc[6] = ffma2(a23, b2,  acc[6]);
            acc[7] = ffma2(a23, b3v, acc[7]);
        }

        // epilogue: softplus + row accumulation + diag capture
        #pragma unroll
        for (int p = 0; p < 2; p++) {
            #pragma unroll
            for (int jj = 0; jj < 4; jj++) {
                float x0, x1; unpack2(acc[p * 4 + jj], x0, x1);
                int jg  = j0c + tj * 4 + jj;
                int ig0 = i0 + ti * 4 + p * 2;
                if (jg == ig0)     g_diag[ig0]     = x0;   // single writer
                if (jg == ig0 + 1) g_diag[ig0 + 1] = x1;
                rowsum[p * 2]     += softplus_f(x0);
                rowsum[p * 2 + 1] += softplus_f(x1);
            }
        }
    }

    // reduce rowsum across the 64 tj-threads sharing each i row
    const int lane = tid & 31, wid = tid >> 5;
    #pragma unroll
    for (int r = 0; r < 4; r++) {
        float v = rowsum[r];
        v += __shfl_down_sync(0xffffffffu, v, 16);
        v += __shfl_down_sync(0xffffffffu, v, 8);
        v += __shfl_down_sync(0xffffffffu, v, 4);
        v += __shfl_down_sync(0xffffffffu, v, 2);
        v += __shfl_down_sync(0xffffffffu, v, 1);
        if (lane == 0) swsum[wid][r] = v;
    }
    __syncthreads();

    if (tid < 16) {
        int r = tid;
        int w0 = (r >> 2) * 2;                       // warps 2*ti, 2*ti+1
        float tot = swsum[w0][r & 3] + swsum[w0 + 1][r & 3];
        g_partial[h * NN + i0 + r] = tot;
    }
}

// ---------------------------------------------------------------------------
// Kernel 3: combine j-halves, finalize loss/MI.
// loss[i] = (sum_{j!=i} softplus(u_ij) - 2047*log2)/2047 - (log2 - softplus(-u_ii))
// ---------------------------------------------------------------------------
__global__ void __launch_bounds__(256) fin_kernel(float* __restrict__ out) {
    int i = blockIdx.x * 256 + threadIdx.x;
    float tot = g_partial[i] + g_partial[NN + i];    // includes diag softplus
    float ud  = g_diag[i];
    float spd = softplus_f(ud);
    float Eneg = (tot - spd - 2047.f * LOG2F_) * (1.f / 2047.f);
    float Epos = LOG2F_ - spd + ud;                  // = log2 - softplus(-u_ii)
    out[i]      = Eneg - Epos;                       // loss
    out[NN + i] = Epos;                              // MI
}

extern "C" void kernel_launch(void* const* d_in, const int* in_sizes, int n_in,
                              void* d_out, int out_size) {
    const float* state  = (const float*)d_in[0];
    const float* action = (const float*)d_in[1];
    const float* W1     = (const float*)d_in[2];
    const float* b1     = (const float*)d_in[3];
    const float* W2     = (const float*)d_in[4];
    const float* b2     = (const float*)d_in[5];
    float* out = (float*)d_out;

    embed_kernel<<<128, 256>>>(state, action, W1, b1, W2, b2);
    jsd_kernel<<<256, 256>>>();
    fin_kernel<<<NN / 256, 256>>>(out);
}

// round 3
// speedup vs baseline: 1.4229x; 1.1402x over previous
#include <cuda_runtime.h>

#define NN 2048
#define LOG2F_ 0.69314718055994530942f

typedef unsigned long long ull;

// Scratch (__device__ globals; no cudaMalloc allowed)
__device__ __align__(16) float g_M1T[32 * NN];   // [u][n] averaged em1, transposed
__device__ __align__(16) float g_M2[NN * 32];    // [n][u] averaged em2
__device__ float g_partial[2 * NN];              // softplus row-sums per j-half
__device__ float g_diag[NN];                     // raw u_ii

// ---- packed f32x2 helpers (FFMA2 path; see SASS_QUICKREF: only via PTX) ----
__device__ __forceinline__ ull pack2(float x, float y) {
    ull r;
    asm("mov.b64 %0, {%1, %2};" : "=l"(r) : "r"(__float_as_uint(x)), "r"(__float_as_uint(y)));
    return r;
}
__device__ __forceinline__ void unpack2(ull v, float& x, float& y) {
    unsigned lo, hi;
    asm("mov.b64 {%0, %1}, %2;" : "=r"(lo), "=r"(hi) : "l"(v));
    x = __uint_as_float(lo); y = __uint_as_float(hi);
}
__device__ __forceinline__ ull ffma2(ull a, ull b, ull c) {
    ull d;
    asm("fma.rn.f32x2 %0, %1, %2, %3;" : "=l"(d) : "l"(a), "l"(b), "l"(c));
    return d;
}

// stable softplus(x) = max(x,0) + log(1 + exp(-|x|))
__device__ __forceinline__ float softplus_f(float x) {
    float a = fabsf(x);
    float l = __logf(1.f + __expf(-a));
    return fmaxf(x, 0.f) + l;
}

// ---------------------------------------------------------------------------
// Kernel 1 (v3): embeddings + leaky_relu + agent-mean, K-SPLIT x4 for
// occupancy. Grid 512 blocks x 256 thr; block handles 4 samples.
// Thread = (nl 0..3, kq 0..3, uh 0..15): computes K-quarter partial dots for
// all 5 agents x 2 units (FFMA2, weight LDS.64 reused across agents).
// Partials reduced in smem (dot is linear in K; bias+leaky+mean afterwards).
// ---------------------------------------------------------------------------
__global__ void __launch_bounds__(256) embed_kernel(
    const float* __restrict__ state, const float* __restrict__ action,
    const float* __restrict__ W1, const float* __restrict__ b1,
    const float* __restrict__ W2, const float* __restrict__ b2) {
    __shared__ __align__(16) float sW1[128 * 32];       // 16 KB
    __shared__ __align__(16) float sW2[64 * 32];        //  8 KB
    __shared__ __align__(8)  float sb1[32], sb2[32];
    __shared__ __align__(16) ull spart1[4][4][5][16];   // 10 KB [nl][kq][a][uh]
    __shared__ __align__(16) ull spart2[4][4][5][16];   // 10 KB

    const int tid = threadIdx.x;
    {   // coalesced float4 weight loads
        const float4* w1v = (const float4*)W1;
        float4* s1v = (float4*)sW1;
        #pragma unroll
        for (int i = 0; i < 4; i++) s1v[tid + i * 256] = w1v[tid + i * 256];
        const float4* w2v = (const float4*)W2;
        float4* s2v = (float4*)sW2;
        #pragma unroll
        for (int i = 0; i < 2; i++) s2v[tid + i * 256] = w2v[tid + i * 256];
        if (tid < 32) { sb1[tid] = b1[tid]; sb2[tid] = b2[tid]; }
    }
    __syncthreads();

    const int nl = tid >> 6, kq = (tid >> 4) & 3, uh = tid & 15, u0 = uh * 2;
    const int n = blockIdx.x * 4 + nl;

    // ---------------- GEMM1 partial: K-quarter of 32 ----------------
    {
        const float* base = state + (size_t)n * 640 + kq * 32;
        ull acc[5];
        #pragma unroll
        for (int a = 0; a < 5; a++) acc[a] = 0ull;

        #pragma unroll
        for (int k4 = 0; k4 < 8; k4++) {
            float4 x[5];
            #pragma unroll
            for (int a = 0; a < 5; a++)
                x[a] = *(const float4*)(base + a * 128 + k4 * 4);
            float xs[5][4];
            #pragma unroll
            for (int a = 0; a < 5; a++) {
                xs[a][0] = x[a].x; xs[a][1] = x[a].y;
                xs[a][2] = x[a].z; xs[a][3] = x[a].w;
            }
            #pragma unroll
            for (int kk = 0; kk < 4; kk++) {
                ull w = *(const ull*)&sW1[(kq * 32 + k4 * 4 + kk) * 32 + u0];
                #pragma unroll
                for (int a = 0; a < 5; a++)
                    acc[a] = ffma2(pack2(xs[a][kk], xs[a][kk]), w, acc[a]);
            }
        }
        #pragma unroll
        for (int a = 0; a < 5; a++) spart1[nl][kq][a][uh] = acc[a];
    }

    // ---------------- GEMM2 partial: K-quarter of 16 ----------------
    {
        const float* base = action + (size_t)n * 320 + kq * 16;
        ull acc[5];
        #pragma unroll
        for (int a = 0; a < 5; a++) acc[a] = 0ull;

        #pragma unroll
        for (int k4 = 0; k4 < 4; k4++) {
            float4 x[5];
            #pragma unroll
            for (int a = 0; a < 5; a++)
                x[a] = *(const float4*)(base + a * 64 + k4 * 4);
            float xs[5][4];
            #pragma unroll
            for (int a = 0; a < 5; a++) {
                xs[a][0] = x[a].x; xs[a][1] = x[a].y;
                xs[a][2] = x[a].z; xs[a][3] = x[a].w;
            }
            #pragma unroll
            for (int kk = 0; kk < 4; kk++) {
                ull w = *(const ull*)&sW2[(kq * 16 + k4 * 4 + kk) * 32 + u0];
                #pragma unroll
                for (int a = 0; a < 5; a++)
                    acc[a] = ffma2(pack2(xs[a][kk], xs[a][kk]), w, acc[a]);
            }
        }
        #pragma unroll
        for (int a = 0; a < 5; a++) spart2[nl][kq][a][uh] = acc[a];
    }

    __syncthreads();

    // ---------------- finalize: 64 threads (nl, uh) ----------------
    if (tid < 64) {
        const int fnl = tid >> 4, fuh = tid & 15, fu0 = fuh * 2;
        const int fn = blockIdx.x * 4 + fnl;

        float bx1, by1; unpack2(*(const ull*)&sb1[fu0], bx1, by1);
        float mx = 0.f, my = 0.f;
        #pragma unroll
        for (int a = 0; a < 5; a++) {
            float vx = bx1, vy = by1;
            #pragma unroll
            for (int q = 0; q < 4; q++) {
                float px, py; unpack2(spart1[fnl][q][a][fuh], px, py);
                vx += px; vy += py;
            }
            mx += (vx > 0.f) ? vx : 0.01f * vx;   // leaky_relu(0.01)
            my += (vy > 0.f) ? vy : 0.01f * vy;
        }
        g_M1T[fu0 * NN + fn]       = 0.2f * mx;
        g_M1T[(fu0 + 1) * NN + fn] = 0.2f * my;

        float bx2, by2; unpack2(*(const ull*)&sb2[fu0], bx2, by2);
        mx = 0.f; my = 0.f;
        #pragma unroll
        for (int a = 0; a < 5; a++) {
            float vx = bx2, vy = by2;
            #pragma unroll
            for (int q = 0; q < 4; q++) {
                float px, py; unpack2(spart2[fnl][q][a][fuh], px, py);
                vx += px; vy += py;
            }
            mx += (vx > 0.f) ? vx : 0.01f * vx;
            my += (vy > 0.f) ? vy : 0.01f * vy;
        }
        *(float2*)&g_M2[fn * 32 + fu0] = make_float2(0.2f * mx, 0.2f * my);
    }
}

// ---------------------------------------------------------------------------
// Kernel 2: fused GEMM (u[i,j] = M2[i].M1[j], K=32) + softplus row-sums.
// grid 256: block = (i-tile ib of 16 rows) x (j-half h of 1024 cols).
// ---------------------------------------------------------------------------
__global__ void __launch_bounds__(256) jsd_kernel() {
    __shared__ __align__(16) float sA[32 * 16];    // [u][ii]  2 KB
    __shared__ __align__(16) float sB[32 * 256];   // [u][jj] 32 KB
    __shared__ float swsum[8][4];

    const int tid = threadIdx.x;
    const int ib = blockIdx.x >> 1, h = blockIdx.x & 1;
    const int i0 = ib * 16, jb = h * 1024;
    const int ti = tid >> 6, tj = tid & 63;

    // stage transposed A tile: sA[u*16+ii] = M2[i0+ii][u]
    for (int t = tid; t < 512; t += 256) {
        int u = t >> 4, ii = t & 15;
        sA[u * 16 + ii] = g_M2[(i0 + ii) * 32 + u];
    }

    float rowsum[4] = {0.f, 0.f, 0.f, 0.f};

    for (int c = 0; c < 4; c++) {
        __syncthreads();
        const int j0c = jb + c * 256;
        #pragma unroll
        for (int t = 0; t < 8; t++) {
            int idx = tid + t * 256;
            int u = idx >> 6, f = (idx & 63) * 4;
            *(float4*)&sB[u * 256 + f] = *(const float4*)&g_M1T[u * NN + j0c + f];
        }
        __syncthreads();

        ull acc[8];
        #pragma unroll
        for (int q = 0; q < 8; q++) acc[q] = 0ull;

        #pragma unroll 8
        for (int u = 0; u < 32; u++) {
            ull a01 = *(const ull*)&sA[u * 16 + ti * 4];
            ull a23 = *(const ull*)&sA[u * 16 + ti * 4 + 2];
            float4 b = *(const float4*)&sB[u * 256 + tj * 4];
            ull b0 = pack2(b.x, b.x), b1v = pack2(b.y, b.y);
            ull b2 = pack2(b.z, b.z), b3v = pack2(b.w, b.w);
            acc[0] = ffma2(a01, b0,  acc[0]);
            acc[1] = ffma2(a01, b1v, acc[1]);
            acc[2] = ffma2(a01, b2,  acc[2]);
            acc[3] = ffma2(a01, b3v, acc[3]);
            acc[4] = ffma2(a23, b0,  acc[4]);
            acc[5] = ffma2(a23, b1v, acc[5]);
            acc[6] = ffma2(a23, b2,  acc[6]);
            acc[7] = ffma2(a23, b3v, acc[7]);
        }

        #pragma unroll
        for (int p = 0; p < 2; p++) {
            #pragma unroll
            for (int jj = 0; jj < 4; jj++) {
                float x0, x1; unpack2(acc[p * 4 + jj], x0, x1);
                int jg  = j0c + tj * 4 + jj;
                int ig0 = i0 + ti * 4 + p * 2;
                if (jg == ig0)     g_diag[ig0]     = x0;   // single writer
                if (jg == ig0 + 1) g_diag[ig0 + 1] = x1;
                rowsum[p * 2]     += softplus_f(x0);
                rowsum[p * 2 + 1] += softplus_f(x1);
            }
        }
    }

    const int lane = tid & 31, wid = tid >> 5;
    #pragma unroll
    for (int r = 0; r < 4; r++) {
        float v = rowsum[r];
        v += __shfl_down_sync(0xffffffffu, v, 16);
        v += __shfl_down_sync(0xffffffffu, v, 8);
        v += __shfl_down_sync(0xffffffffu, v, 4);
        v += __shfl_down_sync(0xffffffffu, v, 2);
        v += __shfl_down_sync(0xffffffffu, v, 1);
        if (lane == 0) swsum[wid][r] = v;
    }
    __syncthreads();

    if (tid < 16) {
        int r = tid;
        int w0 = (r >> 2) * 2;
        float tot = swsum[w0][r & 3] + swsum[w0 + 1][r & 3];
        g_partial[h * NN + i0 + r] = tot;
    }
}

// ---------------------------------------------------------------------------
// Kernel 3: combine j-halves, finalize loss/MI.
// ---------------------------------------------------------------------------
__global__ void __launch_bounds__(256) fin_kernel(float* __restrict__ out) {
    int i = blockIdx.x * 256 + threadIdx.x;
    float tot = g_partial[i] + g_partial[NN + i];    // includes diag softplus
    float ud  = g_diag[i];
    float spd = softplus_f(ud);
    float Eneg = (tot - spd - 2047.f * LOG2F_) * (1.f / 2047.f);
    float Epos = LOG2F_ - spd + ud;                  // = log2 - softplus(-u_ii)
    out[i]      = Eneg - Epos;                       // loss
    out[NN + i] = Epos;                              // MI
}

extern "C" void kernel_launch(void* const* d_in, const int* in_sizes, int n_in,
                              void* d_out, int out_size) {
    const float* state  = (const float*)d_in[0];
    const float* action = (const float*)d_in[1];
    const float* W1     = (const float*)d_in[2];
    const float* b1     = (const float*)d_in[3];
    const float* W2     = (const float*)d_in[4];
    const float* b2     = (const float*)d_in[5];
    float* out = (float*)d_out;

    embed_kernel<<<NN / 4, 256>>>(state, action, W1, b1, W2, b2);
    jsd_kernel<<<256, 256>>>();
    fin_kernel<<<NN / 256, 256>>>(out);
}